// round 15
// baseline (speedup 1.0000x reference)
#include <cuda_runtime.h>
#include <cuda_fp16.h>
#include <math.h>
#include <stdint.h>

#define B_ 2
#define CIN_ 8
#define H_ 224
#define W_ 224
#define F_ 64
#define E_ 8
#define P_ 10
#define S_ 5
#define K_ 7
#define N1_ 43
#define N_ 1849
#define M_ 49
#define D_ 800

typedef unsigned long long ull;
__device__ __forceinline__ void ffma2(ull &d, ull a, ull b){
    asm("fma.rn.f32x2 %0, %1, %2, %0;" : "+l"(d) : "l"(a), "l"(b));
}
__device__ __forceinline__ ull pack2s(float x){
    ull r; asm("mov.b64 %0, {%1, %1};" : "=l"(r) : "f"(x)); return r;
}
__device__ __forceinline__ void unpack2(float &x, float &y, ull v){
    asm("mov.b64 {%0, %1}, %2;" : "=f"(x), "=f"(y) : "l"(v));
}

__device__ float g_t1e[B_*F_*H_*W_];
__device__ float g_t1t[B_*F_*H_*W_];
__device__ float g_t2e[B_*F_*H_*W_];
__device__ float g_t2t[B_*F_*H_*W_];
__device__ float g_xe[B_*E_*H_*W_];
__device__ float g_ltmap[B_*H_*W_];
__device__ float g_pe[B_*N_*D_];
__device__ float g_sq[B_*N_];
__device__ float g_ltm[B_*N_];
__device__ float g_nb[K_*B_*N_*D_];
__device__ float g_wk[B_*N_*400];
__device__ __half g_nhwc[4*226*226*64];
__device__ __half g_bt[2*9*64*64];

__device__ __forceinline__ uint32_t smem_u32(const void* p){
    uint32_t a;
    asm("{ .reg .u64 t; cvta.to.shared.u64 t, %1; cvt.u32.u64 %0, t; }" : "=r"(a) : "l"(p));
    return a;
}
__device__ __forceinline__ void sts32(uint32_t addr, uint32_t v){
    asm volatile("st.shared.b32 [%0], %1;" :: "r"(addr), "r"(v) : "memory");
}
__device__ __forceinline__ void mma_fp16(float* d, const uint32_t* a, uint32_t b0, uint32_t b1){
    asm volatile("mma.sync.aligned.m16n8k16.row.col.f32.f16.f16.f32 "
        "{%0,%1,%2,%3}, {%4,%5,%6,%7}, {%8,%9}, {%0,%1,%2,%3};"
        : "+f"(d[0]),"+f"(d[1]),"+f"(d[2]),"+f"(d[3])
        : "r"(a[0]),"r"(a[1]),"r"(a[2]),"r"(a[3]), "r"(b0),"r"(b1));
}
#define LDSM4(r, addr) \
    asm volatile("ldmatrix.sync.aligned.m8n8.x4.shared.b16 {%0,%1,%2,%3}, [%4];" \
        : "=r"((r)[0]),"=r"((r)[1]),"=r"((r)[2]),"=r"((r)[3]) : "r"(addr))

#define CW2_OFF  46656
#define CSM2_TOT 55872

// ---------- weight fp16 table prep ----------
__global__ void wprep_kernel(const float* __restrict__ w2e, const float* __restrict__ w2t)
{
    int ns = blockIdx.x;
    int net = ns / 9, s = ns % 9;
    int dr = s / 3, dc = s % 3;
    const float* w = net ? w2t : w2e;
    int tid = threadIdx.x;
    for (int j = 0; j < 16; j++){
        int idx = tid + j*256;
        int oc = idx >> 6, ic = idx & 63;
        float v = w[((oc*64 + ic)*3 + dr)*3 + dc];
        g_bt[ns*4096 + idx] = __float2half_rn(v);
    }
}

// ---------- t1 planar fp32 -> padded NHWC fp16 ----------
__global__ void nhwc_convert(const float* __restrict__ t1e, const float* __restrict__ t1t)
{
    __shared__ float s[64][33];
    int bn = blockIdx.x;
    int b = bn >> 1, net = bn & 1;
    int rp = blockIdx.y;
    int cp0 = blockIdx.z * 32;
    int tid = threadIdx.x, lane = tid & 31, wid = tid >> 5;
    int r = rp - 1;
    const float* src = (net ? t1t : t1e) + (size_t)b*F_*H_*W_;

    for (int ic = wid; ic < 64; ic += 8){
        int c = cp0 + lane - 1;
        float v = 0.f;
        if (r >= 0 && r < H_ && c >= 0 && c < W_)
            v = src[(size_t)ic*H_*W_ + r*W_ + c];
        s[ic][lane] = v;
    }
    __syncthreads();

    uint32_t* dst = (uint32_t*)g_nhwc;
    for (int j = 0; j < 4; j++){
        int w = tid + j*256;
        int p = w >> 5, wl = w & 31;
        int cp = cp0 + p;
        if (cp >= 226) continue;
        __half h0 = __float2half_rn(s[2*wl][p]);
        __half h1 = __float2half_rn(s[2*wl+1][p]);
        uint32_t hp = (uint32_t)__half_as_ushort(h0) | ((uint32_t)__half_as_ushort(h1) << 16);
        dst[((size_t)(bn*226 + rp)*226 + cp)*32 + wl] = hp;
    }
}

// ---------- conv2: mma.sync fp16 (unchanged, passing) ----------
__global__ void __launch_bounds__(256, 2)
conv2_mma(const float* __restrict__ b2e, const float* __restrict__ b2t)
{
    extern __shared__ char smem[];
    int bx = blockIdx.x;
    int net = blockIdx.y, b = blockIdx.z;
    int bn = b*2 + net;
    int ty = bx / 14, tx = bx % 14;
    int r0 = ty*16, c0 = tx*16;
    int tid = threadIdx.x, lane = tid & 31, w = tid >> 5;
    uint32_t smb = smem_u32(smem);

    const uint32_t* nh = (const uint32_t*)g_nhwc;
    for (int t = w; t < 324; t += 8){
        int hr = t / 18, hc = t % 18;
        const uint32_t* src = nh + ((size_t)(bn*226 + r0+hr)*226 + (c0+hc))*32;
        sts32(smb + t*144 + lane*4, src[lane]);
    }

    float acc[2][8][4];
    #pragma unroll
    for (int rr=0;rr<2;rr++)
        #pragma unroll
        for (int nt=0;nt<8;nt++)
            #pragma unroll
            for (int i=0;i<4;i++) acc[rr][nt][i]=0.f;

    int m15 = lane & 15;
    uint32_t a_t = smb + (uint32_t)m15*144 + ((lane & 16) ? 16u : 0u);
    int ocb = (lane & 7) + ((lane & 16) ? 8 : 0);
    uint32_t b_base = smb + CW2_OFF + (uint32_t)ocb*144 + ((lane & 8) ? 16u : 0u);

    const uint32_t* bt = (const uint32_t*)g_bt + (size_t)net*9*64*32;

    for (int s = 0; s < 9; s++){
        int dr = s / 3, dc = s % 3;
        __syncthreads();
        for (int rr = w; rr < 64; rr += 8){
            const uint32_t* src = bt + ((size_t)s*2048 + rr*32 + lane);
            sts32(smb + CW2_OFF + rr*144 + lane*4, *src);
        }
        __syncthreads();

        uint32_t a0 = a_t + (uint32_t)((2*w     + dr)*18 + dc)*144;
        uint32_t a1 = a_t + (uint32_t)((2*w + 1 + dr)*18 + dc)*144;
        #pragma unroll
        for (int ks = 0; ks < 4; ks++){
            uint32_t ah0[4], ah1[4];
            LDSM4(ah0, a0 + ks*32);
            LDSM4(ah1, a1 + ks*32);
            #pragma unroll
            for (int p = 0; p < 4; p++){
                uint32_t wh[4];
                LDSM4(wh, b_base + (uint32_t)(p*16)*144 + ks*32);
                mma_fp16(acc[0][2*p],   ah0, wh[0], wh[1]);
                mma_fp16(acc[0][2*p+1], ah0, wh[2], wh[3]);
                mma_fp16(acc[1][2*p],   ah1, wh[0], wh[1]);
                mma_fp16(acc[1][2*p+1], ah1, wh[2], wh[3]);
            }
        }
    }

    const float* bias = net ? b2t : b2e;
    float* outp = (net ? g_t2t : g_t2e) + (size_t)b*F_*H_*W_;
    int pc = lane >> 2;
    int oc_b = (lane & 3) * 2;
    #pragma unroll
    for (int rr = 0; rr < 2; rr++){
        int orow = r0 + 2*w + rr;
        #pragma unroll
        for (int nt = 0; nt < 8; nt++){
            int oc = nt*8 + oc_b;
            float bv0 = bias[oc], bv1 = bias[oc+1];
            size_t base0 = (size_t)oc*(H_*W_) + (size_t)orow*W_ + c0;
            outp[base0 + pc]               = fmaxf(acc[rr][nt][0] + bv0, 0.f);
            outp[base0 + H_*W_ + pc]       = fmaxf(acc[rr][nt][1] + bv1, 0.f);
            outp[base0 + pc + 8]           = fmaxf(acc[rr][nt][2] + bv0, 0.f);
            outp[base0 + H_*W_ + pc + 8]   = fmaxf(acc[rr][nt][3] + bv1, 0.f);
        }
    }
}

// ============ conv1 fused (FFMA2, unchanged) ============
__global__ void __launch_bounds__(256, 2) conv1_fused(
    const float* __restrict__ x,
    const float* __restrict__ wA, const float* __restrict__ bA, float* __restrict__ outA,
    const float* __restrict__ wB, const float* __restrict__ bB, float* __restrict__ outB)
{
    __shared__ float s_in[2][34*34];
    __shared__ __align__(8) float s_w[2][9*16];
    int b = blockIdx.z, oc0 = blockIdx.y * 8;
    int tile = blockIdx.x, tx = tile % 7, ty = tile / 7;
    int x0 = tx*32, y0 = ty*32;
    int tid = threadIdx.x, lx = tid & 31, ly = tid >> 5;

    int goff[5];
    #pragma unroll
    for (int j=0;j<5;j++){
        int i = tid + j*256; goff[j] = -1;
        if (i < 34*34){
            int r = i/34, c = i%34, gr = y0-1+r, gc = x0-1+c;
            goff[j] = (gr>=0 && gr<H_ && gc>=0 && gc<W_) ? gr*W_+gc : -1;
        }
    }
    const float* inbase = x + (size_t)b*CIN_*H_*W_;
    const float* wp = wA; int wslot = 0;
    if (tid < 144){
        int o = tid/9, kk = tid%9;
        wslot = kk*16 + o;
        wp = (o < 8) ? (wA + ((oc0+o)*CIN_)*9 + kk)
                     : (wB + ((oc0+o-8)*CIN_)*9 + kk);
    }
    {
        #pragma unroll
        for (int j=0;j<5;j++){
            int i = tid + j*256;
            if (i < 34*34) s_in[0][i] = (goff[j] >= 0) ? inbase[goff[j]] : 0.f;
        }
        if (tid < 144) s_w[0][wslot] = wp[0];
    }
    __syncthreads();

    ull acc[4][8];
    #pragma unroll
    for (int p=0;p<4;p++)
        #pragma unroll
        for (int o=0;o<8;o++) acc[p][o]=0ull;

    for (int ic=0; ic<CIN_; ic++){
        int buf = ic & 1;
        if (ic+1 < CIN_){
            const float* inp = inbase + (size_t)(ic+1)*H_*W_;
            int nb = buf^1;
            #pragma unroll
            for (int j=0;j<5;j++){
                int i = tid + j*256;
                if (i < 34*34) s_in[nb][i] = (goff[j] >= 0) ? inp[goff[j]] : 0.f;
            }
            if (tid < 144) s_w[nb][wslot] = wp[(ic+1)*9];
        }
        const float* si = s_in[buf];
        #pragma unroll
        for (int dr=0;dr<3;dr++){
            #pragma unroll
            for (int dc=0;dc<3;dc++){
                int kk = dr*3+dc;
                ull v0 = pack2s(si[(ly   +dr)*34 + lx+dc]);
                ull v1 = pack2s(si[(ly+ 8+dr)*34 + lx+dc]);
                ull v2 = pack2s(si[(ly+16+dr)*34 + lx+dc]);
                ull v3 = pack2s(si[(ly+24+dr)*34 + lx+dc]);
                const ull* wrow = (const ull*)&s_w[buf][kk*16];
                #pragma unroll
                for (int op=0;op<8;op++){
                    ull w2 = wrow[op];
                    ffma2(acc[0][op], v0, w2);
                    ffma2(acc[1][op], v1, w2);
                    ffma2(acc[2][op], v2, w2);
                    ffma2(acc[3][op], v3, w2);
                }
            }
        }
        __syncthreads();
    }

    #pragma unroll
    for (int op=0;op<8;op++){
        #pragma unroll
        for (int h=0;h<2;h++){
            int o = op*2+h;
            int oc = oc0 + ((o<8) ? o : o-8);
            float bv = (o<8) ? bA[oc] : bB[oc];
            float* opt = (o<8) ? outA : outB;
            #pragma unroll
            for (int p=0;p<4;p++){
                float a0,a1; unpack2(a0,a1,acc[p][op]);
                float r = fmaxf((h ? a1 : a0) + bv, 0.f);
                opt[((size_t)(b*F_+oc)*H_ + (y0+ly+p*8))*W_ + x0+lx] = r;
            }
        }
    }
}

// ---------------- dual 3x3 conv (layer 3), FFMA2 (unchanged) ----------------
__global__ void __launch_bounds__(256, 4) conv3x3_dual(
    const float* __restrict__ inA, const float* __restrict__ wA,
    const float* __restrict__ bA, float* __restrict__ outA, int CoutA,
    const float* __restrict__ inB, const float* __restrict__ wB,
    const float* __restrict__ bB, float* __restrict__ outB, int CoutB,
    int Cin, int relu, int gA)
{
    __shared__ float s_in[34*34];
    __shared__ __align__(8) float s_w[9*8];
    int b = blockIdx.z, ocg = blockIdx.y;
    const float* in; const float* wgt; const float* bias; float* out; int Cout;
    if (ocg < gA){ in=inA; wgt=wA; bias=bA; out=outA; Cout=CoutA; }
    else { ocg -= gA; in=inB; wgt=wB; bias=bB; out=outB; Cout=CoutB; }

    int tile = blockIdx.x, tx = tile % 7, ty = tile / 7;
    int x0 = tx*32, y0 = ty*32;
    int tid = threadIdx.x, lx = tid & 31, ly = tid >> 5;

    ull acc[4][4];
    #pragma unroll
    for (int p=0;p<4;p++)
        #pragma unroll
        for (int o=0;o<4;o++) acc[p][o]=0ull;

    for (int ic=0; ic<Cin; ic++){
        const float* inp = in + ((size_t)(b*Cin + ic))*H_*W_;
        for (int i=tid; i<34*34; i+=256){
            int r = i/34, c = i%34, gr = y0-1+r, gc = x0-1+c;
            float v = 0.f;
            if (gr>=0 && gr<H_ && gc>=0 && gc<W_) v = inp[gr*W_+gc];
            s_in[i] = v;
        }
        if (tid < 72){
            int o = tid/9, kk = tid%9;
            int oc = ocg*8+o;
            s_w[kk*8+o] = (oc<Cout) ? wgt[(oc*Cin+ic)*9 + kk] : 0.f;
        }
        __syncthreads();
        #pragma unroll
        for (int dr=0;dr<3;dr++){
            #pragma unroll
            for (int dc=0;dc<3;dc++){
                int kk = dr*3+dc;
                ull v0 = pack2s(s_in[(ly   +dr)*34 + lx+dc]);
                ull v1 = pack2s(s_in[(ly+ 8+dr)*34 + lx+dc]);
                ull v2 = pack2s(s_in[(ly+16+dr)*34 + lx+dc]);
                ull v3 = pack2s(s_in[(ly+24+dr)*34 + lx+dc]);
                const ull* wrow = (const ull*)&s_w[kk*8];
                #pragma unroll
                for (int op=0;op<4;op++){
                    ull w2 = wrow[op];
                    ffma2(acc[0][op], v0, w2);
                    ffma2(acc[1][op], v1, w2);
                    ffma2(acc[2][op], v2, w2);
                    ffma2(acc[3][op], v3, w2);
                }
            }
        }
        __syncthreads();
    }

    #pragma unroll
    for (int op=0;op<4;op++){
        #pragma unroll
        for (int h=0;h<2;h++){
            int o = op*2+h;
            int oc = ocg*8+o;
            if (oc < Cout){
                float bv = bias[oc];
                #pragma unroll
                for (int p=0;p<4;p++){
                    float a0,a1; unpack2(a0,a1,acc[p][op]);
                    float r = (h ? a1 : a0) + bv;
                    if (relu) r = fmaxf(r, 0.f);
                    out[((size_t)(b*Cout+oc)*H_ + (y0+ly+p*8))*W_ + x0+lx] = r;
                }
            }
        }
    }
}

// ---------------- patches (unchanged) ----------------
__global__ void patches_kernel()
{
    int bn = blockIdx.x;
    int b = bn / N_, n = bn % N_;
    int n1 = n / N1_, n2 = n % N1_;
    int r0 = n1*S_, c0 = n2*S_;
    int tid = threadIdx.x;

    float loc = 0.f;
    for (int d=tid; d<D_; d+=128){
        int c = d/100, rem = d%100, p1 = rem/10, p2 = rem%10;
        float v = g_xe[((b*E_+c)*H_ + r0+p1)*W_ + c0+p2];
        g_pe[(size_t)bn*D_ + d] = v;
        loc += v*v;
    }
    float lv = 0.f;
    if (tid < 100){
        int p1 = tid/10, p2 = tid%10;
        lv = g_ltmap[(b*H_ + r0+p1)*W_ + c0+p2];
    }
    __shared__ float r1s[4], r2s[4];
    int lane = tid & 31, wid = tid >> 5;
    #pragma unroll
    for (int off=16; off; off>>=1){
        loc += __shfl_xor_sync(0xffffffffu, loc, off);
        lv  += __shfl_xor_sync(0xffffffffu, lv,  off);
    }
    if (lane==0){ r1s[wid]=loc; r2s[wid]=lv; }
    __syncthreads();
    if (tid==0){
        g_sq[bn]  = r1s[0]+r1s[1]+r1s[2]+r1s[3];
        g_ltm[bn] = (r2s[0]+r2s[1]+r2s[2]+r2s[3]) * (1.f/100.f);
    }
}

// ------- dist_q4: 2x2 query tiling, distances + K softmax -> g_wk -------
__global__ void __launch_bounds__(256) dist_q4()
{
    __shared__ float s_q[3200];
    __shared__ __align__(16) float s_wk[4][M_][8];
    __shared__ float s_dot[64][4];
    __shared__ int s_u1[8], s_u2[8], s_qn[4], s_valid[4];
    __shared__ float s_sqq[4], s_scale[4];

    int t = blockIdx.x;
    int b = t / 484; int rem = t % 484;
    int t1 = rem / 22, t2 = rem % 22;
    int tid = threadIdx.x, lane = tid & 31, w = tid >> 5;

    if (tid < 8){
        s_u1[tid] = min(max(2*t1-3+tid, 0), 42);
        s_u2[tid] = min(max(2*t2-3+tid, 0), 42);
    }
    if (tid < 4){
        int iq = tid >> 1, jq = tid & 1;
        int q1r = 2*t1+iq, q2r = 2*t2+jq;
        s_valid[tid] = (q1r <= 42 && q2r <= 42) ? 1 : 0;
        int q1 = min(q1r, 42), q2 = min(q2r, 42);
        int qn = q1*43 + q2;
        s_qn[tid] = qn;
        s_sqq[tid] = g_sq[b*N_+qn];
        s_scale[tid] = expf(-g_ltm[b*N_+qn]);
    }
    #pragma unroll
    for (int qq = 0; qq < 4; qq++){
        int q1 = min(2*t1 + (qq>>1), 42), q2 = min(2*t2 + (qq&1), 42);
        const float4* src = (const float4*)(g_pe + (size_t)(b*N_ + q1*43+q2)*D_);
        if (tid < 200) ((float4*)(s_q + qq*800))[tid] = src[tid];
    }
    __syncthreads();

    const float4* sq0 = (const float4*)(s_q);
    const float4* sq1 = (const float4*)(s_q + 800);
    const float4* sq2 = (const float4*)(s_q + 1600);
    const float4* sq3 = (const float4*)(s_q + 2400);
    for (int m = w; m < 64; m += 8){
        int i = m >> 3, j = m & 7;
        int cand = s_u1[i]*43 + s_u2[j];
        const float4* pc = (const float4*)(g_pe + (size_t)(b*N_+cand)*D_);
        float d0=0.f, d1=0.f, d2=0.f, d3=0.f;
        #pragma unroll
        for (int jj = 0; jj < 6; jj++){
            float4 a = pc[lane + jj*32];
            float4 v;
            v = sq0[lane+jj*32]; d0 = fmaf(a.x,v.x,fmaf(a.y,v.y,fmaf(a.z,v.z,fmaf(a.w,v.w,d0))));
            v = sq1[lane+jj*32]; d1 = fmaf(a.x,v.x,fmaf(a.y,v.y,fmaf(a.z,v.z,fmaf(a.w,v.w,d1))));
            v = sq2[lane+jj*32]; d2 = fmaf(a.x,v.x,fmaf(a.y,v.y,fmaf(a.z,v.z,fmaf(a.w,v.w,d2))));
            v = sq3[lane+jj*32]; d3 = fmaf(a.x,v.x,fmaf(a.y,v.y,fmaf(a.z,v.z,fmaf(a.w,v.w,d3))));
        }
        if (lane < 8){
            float4 a = pc[192+lane];
            float4 v;
            v = sq0[192+lane]; d0 = fmaf(a.x,v.x,fmaf(a.y,v.y,fmaf(a.z,v.z,fmaf(a.w,v.w,d0))));
            v = sq1[192+lane]; d1 = fmaf(a.x,v.x,fmaf(a.y,v.y,fmaf(a.z,v.z,fmaf(a.w,v.w,d1))));
            v = sq2[192+lane]; d2 = fmaf(a.x,v.x,fmaf(a.y,v.y,fmaf(a.z,v.z,fmaf(a.w,v.w,d2))));
            v = sq3[192+lane]; d3 = fmaf(a.x,v.x,fmaf(a.y,v.y,fmaf(a.z,v.z,fmaf(a.w,v.w,d3))));
        }
        #pragma unroll
        for (int off=16; off; off>>=1){
            d0 += __shfl_xor_sync(0xffffffffu, d0, off);
            d1 += __shfl_xor_sync(0xffffffffu, d1, off);
            d2 += __shfl_xor_sync(0xffffffffu, d2, off);
            d3 += __shfl_xor_sync(0xffffffffu, d3, off);
        }
        if (lane == 0){
            float sqc = g_sq[b*N_+cand];
            s_dot[m][0] = (cand==s_qn[0]) ? -1e9f : -(s_sqq[0]+sqc-2.f*d0)*s_scale[0];
            s_dot[m][1] = (cand==s_qn[1]) ? -1e9f : -(s_sqq[1]+sqc-2.f*d1)*s_scale[1];
            s_dot[m][2] = (cand==s_qn[2]) ? -1e9f : -(s_sqq[2]+sqc-2.f*d2)*s_scale[2];
            s_dot[m][3] = (cand==s_qn[3]) ? -1e9f : -(s_sqq[3]+sqc-2.f*d3)*s_scale[3];
        }
    }
    __syncthreads();

    if (w < 4){
        int iq = w >> 1, jq = w & 1;
        int i1 = lane/7, j1 = lane%7;
        float a = s_dot[(i1+iq)*8 + (j1+jq)][w];
        int idx2 = lane + 32;
        bool hasb = idx2 < M_;
        float bvl = -INFINITY;
        if (hasb){ int i2 = idx2/7, j2 = idx2%7; bvl = s_dot[(i2+iq)*8 + (j2+jq)][w]; }
        #pragma unroll
        for (int k=0;k<K_;k++){
            float mx = fmaxf(a, bvl);
            #pragma unroll
            for (int off=16; off; off>>=1) mx = fmaxf(mx, __shfl_xor_sync(0xffffffffu, mx, off));
            float ea = expf(a - mx);
            float eb = hasb ? expf(bvl - mx) : 0.f;
            float ssum = ea + eb;
            #pragma unroll
            for (int off=16; off; off>>=1) ssum += __shfl_xor_sync(0xffffffffu, ssum, off);
            float inv = 1.f/ssum;
            float wa = ea*inv, wb = eb*inv;
            s_wk[w][lane][k] = wa;
            if (hasb) s_wk[w][idx2][k] = wb;
            a   += log1pf(-fminf(wa, 1.f-1e-6f));
            bvl += log1pf(-fminf(wb, 1.f-1e-6f));
        }
    }
    __syncthreads();

    // write Wk for valid queries (coalesced float4: 98 per query)
    #pragma unroll
    for (int qq = 0; qq < 4; qq++){
        if (!s_valid[qq]) continue;
        float4* dst = (float4*)(g_wk + (size_t)(b*N_ + s_qn[qq])*400);
        const float4* src = (const float4*)&s_wk[qq][0][0];
        if (tid < 98) dst[tid] = src[tid];
    }
}

// ------- agg: x-union staging + Wk -> g_nb (R11 aggregation) -------
__global__ void __launch_bounds__(256) agg_kernel(const float* __restrict__ x)
{
    extern __shared__ float sm[];
    float* s_xf = sm;                 // 12800
    __shared__ __align__(16) float s_wk[M_][8];
    __shared__ int s_off[M_];

    int bn = blockIdx.x;
    int b = bn / N_, n = bn % N_;
    int q1 = n / N1_, q2 = n % N1_;
    int tid = threadIdx.x, lane = tid & 31, wid = tid >> 5;

    int c1lo = max(q1-3,0);
    int c2lo = max(q2-3,0);
    int rows = (min(q1+3, N1_-1)-c1lo)*S_ + P_;
    int cols = (min(q2+3, N1_-1)-c2lo)*S_ + P_;
    int r0 = c1lo*S_, c0 = c2lo*S_;

    if (tid < M_){
        int i = tid/7, j = tid%7;
        int c1 = min(max(q1+i-3,0), N1_-1);
        int c2 = min(max(q2+j-3,0), N1_-1);
        s_off[tid]  = ((c1-c1lo)*S_)*40 + (c2-c2lo)*S_;
    }
    if (tid < 98)
        ((float4*)&s_wk[0][0])[tid] = ((const float4*)(g_wk + (size_t)bn*400))[tid];

    #pragma unroll
    for (int c=0;c<CIN_;c++){
        const float* src = x + ((size_t)(b*CIN_+c)*H_ + r0)*W_ + c0;
        for (int r=wid; r<rows; r+=8)
            for (int cc=lane; cc<cols; cc+=32)
                s_xf[c*1600 + r*40 + cc] = src[r*W_ + cc];
    }
    __syncthreads();

    int baseidx[4]; bool act[4];
    #pragma unroll
    for (int j=0;j<4;j++){
        int d = tid + 256*j;
        act[j] = (d < D_);
        int dd = act[j] ? d : 0;
        int c = dd/100, rem = dd%100, p1 = rem/10, p2 = rem%10;
        baseidx[j] = c*1600 + p1*40 + p2;
    }
    ull a01[4], a23[4], a45[4];
    float a6[4];
    #pragma unroll
    for (int j=0;j<4;j++){ a01[j]=0ull; a23[j]=0ull; a45[j]=0ull; a6[j]=0.f; }

    for (int m=0;m<M_;m++){
        int o = s_off[m];
        const ull* wr = (const ull*)&s_wk[m][0];
        ull w01 = wr[0], w23 = wr[1], w45 = wr[2];
        float w6 = s_wk[m][6];
        #pragma unroll
        for (int j=0;j<4;j++){
            float v = s_xf[baseidx[j]+o];
            ull vv = pack2s(v);
            ffma2(a01[j], vv, w01);
            ffma2(a23[j], vv, w23);
            ffma2(a45[j], vv, w45);
            a6[j] = fmaf(w6, v, a6[j]);
        }
    }
    #pragma unroll
    for (int j=0;j<4;j++){
        if (!act[j]) continue;
        int d = tid + 256*j;
        float o0,o1,o2,o3,o4,o5;
        unpack2(o0,o1,a01[j]); unpack2(o2,o3,a23[j]); unpack2(o4,o5,a45[j]);
        float vals[7] = {o0,o1,o2,o3,o4,o5,a6[j]};
        #pragma unroll
        for (int k=0;k<K_;k++)
            g_nb[((size_t)(k*B_+b)*N_ + n)*D_ + d] = vals[k];
    }
}

// ---------------- fold (unchanged) ----------------
__global__ void fold_kernel(const float* __restrict__ x, float* __restrict__ out)
{
    int idx = blockIdx.x*blockDim.x + threadIdx.x;
    const int total = B_*(K_+1)*CIN_*H_*W_;
    if (idx >= total) return;
    int w  = idx % W_;
    int r  = (idx / W_) % H_;
    int ch = (idx / (H_*W_)) % ((K_+1)*CIN_);
    int b  = idx / (H_*W_*(K_+1)*CIN_);

    if (ch < CIN_){
        out[idx] = x[((b*CIN_+ch)*H_+r)*W_+w];
        return;
    }
    int k = (ch - CIN_) / CIN_;
    int c = (ch - CIN_) % CIN_;

    int n1lo = (r >= P_-1) ? (r-(P_-1)+S_-1)/S_ : 0;
    int n1hi = min(N1_-1, r/S_);
    int n2lo = (w >= P_-1) ? (w-(P_-1)+S_-1)/S_ : 0;
    int n2hi = min(N1_-1, w/S_);

    float sum = 0.f; int cnt = 0;
    for (int n1=n1lo; n1<=n1hi; n1++){
        int p1 = r - n1*S_;
        for (int n2=n2lo; n2<=n2hi; n2++){
            int p2 = w - n2*S_;
            sum += g_nb[((size_t)(k*B_+b)*N_ + n1*N1_+n2)*D_ + c*100 + p1*10 + p2];
            cnt++;
        }
    }
    out[idx] = (cnt > 0) ? sum/(float)cnt : 0.f;
}

// ---------------- launch ----------------
extern "C" void kernel_launch(void* const* d_in, const int* in_sizes, int n_in,
                              void* d_out, int out_size)
{
    const float* x   = (const float*)d_in[0];
    const float* w1e = (const float*)d_in[1];
    const float* b1e = (const float*)d_in[2];
    const float* w2e = (const float*)d_in[3];
    const float* b2e = (const float*)d_in[4];
    const float* w3e = (const float*)d_in[5];
    const float* b3e = (const float*)d_in[6];
    const float* w1t = (const float*)d_in[7];
    const float* b1t = (const float*)d_in[8];
    const float* w2t = (const float*)d_in[9];
    const float* b2t = (const float*)d_in[10];
    const float* w3t = (const float*)d_in[11];
    const float* b3t = (const float*)d_in[12];

    float *t1e, *t1t, *t2e, *t2t, *xe, *ltmap;
    cudaGetSymbolAddress((void**)&t1e,   g_t1e);
    cudaGetSymbolAddress((void**)&t1t,   g_t1t);
    cudaGetSymbolAddress((void**)&t2e,   g_t2e);
    cudaGetSymbolAddress((void**)&t2t,   g_t2t);
    cudaGetSymbolAddress((void**)&xe,    g_xe);
    cudaGetSymbolAddress((void**)&ltmap, g_ltmap);

    static int attr_done = 0;
    if (!attr_done){
        cudaFuncSetAttribute(agg_kernel,
                             cudaFuncAttributeMaxDynamicSharedMemorySize, 56*1024);
        cudaFuncSetAttribute(conv2_mma,
                             cudaFuncAttributeMaxDynamicSharedMemorySize, CSM2_TOT);
        attr_done = 1;
    }

    conv1_fused<<<dim3(49,8,B_), 256>>>(x, w1e, b1e, t1e, w1t, b1t, t1t);
    wprep_kernel<<<18, 256>>>(w2e, w2t);
    nhwc_convert<<<dim3(4,226,8), 256>>>(t1e, t1t);
    conv2_mma<<<dim3(196,2,2), 256, CSM2_TOT>>>(b2e, b2t);
    conv3x3_dual<<<dim3(49,2,B_), 256>>>(t2e, w3e, b3e, xe,    E_,
                                         t2t, w3t, b3t, ltmap, 1, F_, 0, 1);

    patches_kernel<<<B_*N_, 128>>>();
    dist_q4<<<B_*484, 256>>>();
    agg_kernel<<<B_*N_, 256, 12800*sizeof(float)>>>(x);

    const int total = B_*(K_+1)*CIN_*H_*W_;
    fold_kernel<<<(total+255)/256, 256>>>(x, (float*)d_out);
}

// round 16
// speedup vs baseline: 1.1219x; 1.1219x over previous
#include <cuda_runtime.h>
#include <cuda_fp16.h>
#include <math.h>
#include <stdint.h>

#define B_ 2
#define CIN_ 8
#define H_ 224
#define W_ 224
#define F_ 64
#define E_ 8
#define P_ 10
#define S_ 5
#define K_ 7
#define N1_ 43
#define N_ 1849
#define M_ 49
#define D_ 800

typedef unsigned long long ull;
__device__ __forceinline__ void ffma2(ull &d, ull a, ull b){
    asm("fma.rn.f32x2 %0, %1, %2, %0;" : "+l"(d) : "l"(a), "l"(b));
}
__device__ __forceinline__ ull pack2s(float x){
    ull r; asm("mov.b64 %0, {%1, %1};" : "=l"(r) : "f"(x)); return r;
}
__device__ __forceinline__ void unpack2(float &x, float &y, ull v){
    asm("mov.b64 {%0, %1}, %2;" : "=f"(x), "=f"(y) : "l"(v));
}

__device__ float g_t1e[B_*F_*H_*W_];
__device__ float g_t1t[B_*F_*H_*W_];
__device__ float g_t2e[B_*F_*H_*W_];
__device__ float g_t2t[B_*F_*H_*W_];
__device__ float g_xe[B_*E_*H_*W_];
__device__ float g_ltmap[B_*H_*W_];
__device__ float g_pe[B_*N_*D_];
__device__ float g_sq[B_*N_];
__device__ float g_ltm[B_*N_];
__device__ float g_nb[K_*B_*N_*D_];
__device__ __half g_nhwc[4*226*226*64];
__device__ __half g_bt[2*9*64*64];

__device__ __forceinline__ uint32_t smem_u32(const void* p){
    uint32_t a;
    asm("{ .reg .u64 t; cvta.to.shared.u64 t, %1; cvt.u32.u64 %0, t; }" : "=r"(a) : "l"(p));
    return a;
}
__device__ __forceinline__ void sts32(uint32_t addr, uint32_t v){
    asm volatile("st.shared.b32 [%0], %1;" :: "r"(addr), "r"(v) : "memory");
}
__device__ __forceinline__ void mma_fp16(float* d, const uint32_t* a, uint32_t b0, uint32_t b1){
    asm volatile("mma.sync.aligned.m16n8k16.row.col.f32.f16.f16.f32 "
        "{%0,%1,%2,%3}, {%4,%5,%6,%7}, {%8,%9}, {%0,%1,%2,%3};"
        : "+f"(d[0]),"+f"(d[1]),"+f"(d[2]),"+f"(d[3])
        : "r"(a[0]),"r"(a[1]),"r"(a[2]),"r"(a[3]), "r"(b0),"r"(b1));
}
#define LDSM4(r, addr) \
    asm volatile("ldmatrix.sync.aligned.m8n8.x4.shared.b16 {%0,%1,%2,%3}, [%4];" \
        : "=r"((r)[0]),"=r"((r)[1]),"=r"((r)[2]),"=r"((r)[3]) : "r"(addr))

#define CW2_OFF  46656
#define CSM2_TOT 55872

// ---------- weight fp16 table prep ----------
__global__ void wprep_kernel(const float* __restrict__ w2e, const float* __restrict__ w2t)
{
    int ns = blockIdx.x;
    int net = ns / 9, s = ns % 9;
    int dr = s / 3, dc = s % 3;
    const float* w = net ? w2t : w2e;
    int tid = threadIdx.x;
    for (int j = 0; j < 16; j++){
        int idx = tid + j*256;
        int oc = idx >> 6, ic = idx & 63;
        float v = w[((oc*64 + ic)*3 + dr)*3 + dc];
        g_bt[ns*4096 + idx] = __float2half_rn(v);
    }
}

// ---------- t1 planar fp32 -> padded NHWC fp16 ----------
__global__ void nhwc_convert(const float* __restrict__ t1e, const float* __restrict__ t1t)
{
    __shared__ float s[64][33];
    int bn = blockIdx.x;
    int b = bn >> 1, net = bn & 1;
    int rp = blockIdx.y;
    int cp0 = blockIdx.z * 32;
    int tid = threadIdx.x, lane = tid & 31, wid = tid >> 5;
    int r = rp - 1;
    const float* src = (net ? t1t : t1e) + (size_t)b*F_*H_*W_;

    for (int ic = wid; ic < 64; ic += 8){
        int c = cp0 + lane - 1;
        float v = 0.f;
        if (r >= 0 && r < H_ && c >= 0 && c < W_)
            v = src[(size_t)ic*H_*W_ + r*W_ + c];
        s[ic][lane] = v;
    }
    __syncthreads();

    uint32_t* dst = (uint32_t*)g_nhwc;
    for (int j = 0; j < 4; j++){
        int w = tid + j*256;
        int p = w >> 5, wl = w & 31;
        int cp = cp0 + p;
        if (cp >= 226) continue;
        __half h0 = __float2half_rn(s[2*wl][p]);
        __half h1 = __float2half_rn(s[2*wl+1][p]);
        uint32_t hp = (uint32_t)__half_as_ushort(h0) | ((uint32_t)__half_as_ushort(h1) << 16);
        dst[((size_t)(bn*226 + rp)*226 + cp)*32 + wl] = hp;
    }
}

// ---------- conv2: mma.sync fp16 (unchanged, passing) ----------
__global__ void __launch_bounds__(256, 2)
conv2_mma(const float* __restrict__ b2e, const float* __restrict__ b2t)
{
    extern __shared__ char smem[];
    int bx = blockIdx.x;
    int net = blockIdx.y, b = blockIdx.z;
    int bn = b*2 + net;
    int ty = bx / 14, tx = bx % 14;
    int r0 = ty*16, c0 = tx*16;
    int tid = threadIdx.x, lane = tid & 31, w = tid >> 5;
    uint32_t smb = smem_u32(smem);

    const uint32_t* nh = (const uint32_t*)g_nhwc;
    for (int t = w; t < 324; t += 8){
        int hr = t / 18, hc = t % 18;
        const uint32_t* src = nh + ((size_t)(bn*226 + r0+hr)*226 + (c0+hc))*32;
        sts32(smb + t*144 + lane*4, src[lane]);
    }

    float acc[2][8][4];
    #pragma unroll
    for (int rr=0;rr<2;rr++)
        #pragma unroll
        for (int nt=0;nt<8;nt++)
            #pragma unroll
            for (int i=0;i<4;i++) acc[rr][nt][i]=0.f;

    int m15 = lane & 15;
    uint32_t a_t = smb + (uint32_t)m15*144 + ((lane & 16) ? 16u : 0u);
    int ocb = (lane & 7) + ((lane & 16) ? 8 : 0);
    uint32_t b_base = smb + CW2_OFF + (uint32_t)ocb*144 + ((lane & 8) ? 16u : 0u);

    const uint32_t* bt = (const uint32_t*)g_bt + (size_t)net*9*64*32;

    for (int s = 0; s < 9; s++){
        int dr = s / 3, dc = s % 3;
        __syncthreads();
        for (int rr = w; rr < 64; rr += 8){
            const uint32_t* src = bt + ((size_t)s*2048 + rr*32 + lane);
            sts32(smb + CW2_OFF + rr*144 + lane*4, *src);
        }
        __syncthreads();

        uint32_t a0 = a_t + (uint32_t)((2*w     + dr)*18 + dc)*144;
        uint32_t a1 = a_t + (uint32_t)((2*w + 1 + dr)*18 + dc)*144;
        #pragma unroll
        for (int ks = 0; ks < 4; ks++){
            uint32_t ah0[4], ah1[4];
            LDSM4(ah0, a0 + ks*32);
            LDSM4(ah1, a1 + ks*32);
            #pragma unroll
            for (int p = 0; p < 4; p++){
                uint32_t wh[4];
                LDSM4(wh, b_base + (uint32_t)(p*16)*144 + ks*32);
                mma_fp16(acc[0][2*p],   ah0, wh[0], wh[1]);
                mma_fp16(acc[0][2*p+1], ah0, wh[2], wh[3]);
                mma_fp16(acc[1][2*p],   ah1, wh[0], wh[1]);
                mma_fp16(acc[1][2*p+1], ah1, wh[2], wh[3]);
            }
        }
    }

    const float* bias = net ? b2t : b2e;
    float* outp = (net ? g_t2t : g_t2e) + (size_t)b*F_*H_*W_;
    int pc = lane >> 2;
    int oc_b = (lane & 3) * 2;
    #pragma unroll
    for (int rr = 0; rr < 2; rr++){
        int orow = r0 + 2*w + rr;
        #pragma unroll
        for (int nt = 0; nt < 8; nt++){
            int oc = nt*8 + oc_b;
            float bv0 = bias[oc], bv1 = bias[oc+1];
            size_t base0 = (size_t)oc*(H_*W_) + (size_t)orow*W_ + c0;
            outp[base0 + pc]               = fmaxf(acc[rr][nt][0] + bv0, 0.f);
            outp[base0 + H_*W_ + pc]       = fmaxf(acc[rr][nt][1] + bv1, 0.f);
            outp[base0 + pc + 8]           = fmaxf(acc[rr][nt][2] + bv0, 0.f);
            outp[base0 + H_*W_ + pc + 8]   = fmaxf(acc[rr][nt][3] + bv1, 0.f);
        }
    }
}

// ============ conv1 fused (FFMA2, unchanged) ============
__global__ void __launch_bounds__(256, 2) conv1_fused(
    const float* __restrict__ x,
    const float* __restrict__ wA, const float* __restrict__ bA, float* __restrict__ outA,
    const float* __restrict__ wB, const float* __restrict__ bB, float* __restrict__ outB)
{
    __shared__ float s_in[2][34*34];
    __shared__ __align__(8) float s_w[2][9*16];
    int b = blockIdx.z, oc0 = blockIdx.y * 8;
    int tile = blockIdx.x, tx = tile % 7, ty = tile / 7;
    int x0 = tx*32, y0 = ty*32;
    int tid = threadIdx.x, lx = tid & 31, ly = tid >> 5;

    int goff[5];
    #pragma unroll
    for (int j=0;j<5;j++){
        int i = tid + j*256; goff[j] = -1;
        if (i < 34*34){
            int r = i/34, c = i%34, gr = y0-1+r, gc = x0-1+c;
            goff[j] = (gr>=0 && gr<H_ && gc>=0 && gc<W_) ? gr*W_+gc : -1;
        }
    }
    const float* inbase = x + (size_t)b*CIN_*H_*W_;
    const float* wp = wA; int wslot = 0;
    if (tid < 144){
        int o = tid/9, kk = tid%9;
        wslot = kk*16 + o;
        wp = (o < 8) ? (wA + ((oc0+o)*CIN_)*9 + kk)
                     : (wB + ((oc0+o-8)*CIN_)*9 + kk);
    }
    {
        #pragma unroll
        for (int j=0;j<5;j++){
            int i = tid + j*256;
            if (i < 34*34) s_in[0][i] = (goff[j] >= 0) ? inbase[goff[j]] : 0.f;
        }
        if (tid < 144) s_w[0][wslot] = wp[0];
    }
    __syncthreads();

    ull acc[4][8];
    #pragma unroll
    for (int p=0;p<4;p++)
        #pragma unroll
        for (int o=0;o<8;o++) acc[p][o]=0ull;

    for (int ic=0; ic<CIN_; ic++){
        int buf = ic & 1;
        if (ic+1 < CIN_){
            const float* inp = inbase + (size_t)(ic+1)*H_*W_;
            int nb = buf^1;
            #pragma unroll
            for (int j=0;j<5;j++){
                int i = tid + j*256;
                if (i < 34*34) s_in[nb][i] = (goff[j] >= 0) ? inp[goff[j]] : 0.f;
            }
            if (tid < 144) s_w[nb][wslot] = wp[(ic+1)*9];
        }
        const float* si = s_in[buf];
        #pragma unroll
        for (int dr=0;dr<3;dr++){
            #pragma unroll
            for (int dc=0;dc<3;dc++){
                int kk = dr*3+dc;
                ull v0 = pack2s(si[(ly   +dr)*34 + lx+dc]);
                ull v1 = pack2s(si[(ly+ 8+dr)*34 + lx+dc]);
                ull v2 = pack2s(si[(ly+16+dr)*34 + lx+dc]);
                ull v3 = pack2s(si[(ly+24+dr)*34 + lx+dc]);
                const ull* wrow = (const ull*)&s_w[buf][kk*16];
                #pragma unroll
                for (int op=0;op<8;op++){
                    ull w2 = wrow[op];
                    ffma2(acc[0][op], v0, w2);
                    ffma2(acc[1][op], v1, w2);
                    ffma2(acc[2][op], v2, w2);
                    ffma2(acc[3][op], v3, w2);
                }
            }
        }
        __syncthreads();
    }

    #pragma unroll
    for (int op=0;op<8;op++){
        #pragma unroll
        for (int h=0;h<2;h++){
            int o = op*2+h;
            int oc = oc0 + ((o<8) ? o : o-8);
            float bv = (o<8) ? bA[oc] : bB[oc];
            float* opt = (o<8) ? outA : outB;
            #pragma unroll
            for (int p=0;p<4;p++){
                float a0,a1; unpack2(a0,a1,acc[p][op]);
                float r = fmaxf((h ? a1 : a0) + bv, 0.f);
                opt[((size_t)(b*F_+oc)*H_ + (y0+ly+p*8))*W_ + x0+lx] = r;
            }
        }
    }
}

// ---------------- dual 3x3 conv (layer 3), FFMA2 (unchanged) ----------------
__global__ void __launch_bounds__(256, 4) conv3x3_dual(
    const float* __restrict__ inA, const float* __restrict__ wA,
    const float* __restrict__ bA, float* __restrict__ outA, int CoutA,
    const float* __restrict__ inB, const float* __restrict__ wB,
    const float* __restrict__ bB, float* __restrict__ outB, int CoutB,
    int Cin, int relu, int gA)
{
    __shared__ float s_in[34*34];
    __shared__ __align__(8) float s_w[9*8];
    int b = blockIdx.z, ocg = blockIdx.y;
    const float* in; const float* wgt; const float* bias; float* out; int Cout;
    if (ocg < gA){ in=inA; wgt=wA; bias=bA; out=outA; Cout=CoutA; }
    else { ocg -= gA; in=inB; wgt=wB; bias=bB; out=outB; Cout=CoutB; }

    int tile = blockIdx.x, tx = tile % 7, ty = tile / 7;
    int x0 = tx*32, y0 = ty*32;
    int tid = threadIdx.x, lx = tid & 31, ly = tid >> 5;

    ull acc[4][4];
    #pragma unroll
    for (int p=0;p<4;p++)
        #pragma unroll
        for (int o=0;o<4;o++) acc[p][o]=0ull;

    for (int ic=0; ic<Cin; ic++){
        const float* inp = in + ((size_t)(b*Cin + ic))*H_*W_;
        for (int i=tid; i<34*34; i+=256){
            int r = i/34, c = i%34, gr = y0-1+r, gc = x0-1+c;
            float v = 0.f;
            if (gr>=0 && gr<H_ && gc>=0 && gc<W_) v = inp[gr*W_+gc];
            s_in[i] = v;
        }
        if (tid < 72){
            int o = tid/9, kk = tid%9;
            int oc = ocg*8+o;
            s_w[kk*8+o] = (oc<Cout) ? wgt[(oc*Cin+ic)*9 + kk] : 0.f;
        }
        __syncthreads();
        #pragma unroll
        for (int dr=0;dr<3;dr++){
            #pragma unroll
            for (int dc=0;dc<3;dc++){
                int kk = dr*3+dc;
                ull v0 = pack2s(s_in[(ly   +dr)*34 + lx+dc]);
                ull v1 = pack2s(s_in[(ly+ 8+dr)*34 + lx+dc]);
                ull v2 = pack2s(s_in[(ly+16+dr)*34 + lx+dc]);
                ull v3 = pack2s(s_in[(ly+24+dr)*34 + lx+dc]);
                const ull* wrow = (const ull*)&s_w[kk*8];
                #pragma unroll
                for (int op=0;op<4;op++){
                    ull w2 = wrow[op];
                    ffma2(acc[0][op], v0, w2);
                    ffma2(acc[1][op], v1, w2);
                    ffma2(acc[2][op], v2, w2);
                    ffma2(acc[3][op], v3, w2);
                }
            }
        }
        __syncthreads();
    }

    #pragma unroll
    for (int op=0;op<4;op++){
        #pragma unroll
        for (int h=0;h<2;h++){
            int o = op*2+h;
            int oc = ocg*8+o;
            if (oc < Cout){
                float bv = bias[oc];
                #pragma unroll
                for (int p=0;p<4;p++){
                    float a0,a1; unpack2(a0,a1,acc[p][op]);
                    float r = (h ? a1 : a0) + bv;
                    if (relu) r = fmaxf(r, 0.f);
                    out[((size_t)(b*Cout+oc)*H_ + (y0+ly+p*8))*W_ + x0+lx] = r;
                }
            }
        }
    }
}

// ---------------- patches (unchanged) ----------------
__global__ void patches_kernel()
{
    int bn = blockIdx.x;
    int b = bn / N_, n = bn % N_;
    int n1 = n / N1_, n2 = n % N1_;
    int r0 = n1*S_, c0 = n2*S_;
    int tid = threadIdx.x;

    float loc = 0.f;
    for (int d=tid; d<D_; d+=128){
        int c = d/100, rem = d%100, p1 = rem/10, p2 = rem%10;
        float v = g_xe[((b*E_+c)*H_ + r0+p1)*W_ + c0+p2];
        g_pe[(size_t)bn*D_ + d] = v;
        loc += v*v;
    }
    float lv = 0.f;
    if (tid < 100){
        int p1 = tid/10, p2 = tid%10;
        lv = g_ltmap[(b*H_ + r0+p1)*W_ + c0+p2];
    }
    __shared__ float r1s[4], r2s[4];
    int lane = tid & 31, wid = tid >> 5;
    #pragma unroll
    for (int off=16; off; off>>=1){
        loc += __shfl_xor_sync(0xffffffffu, loc, off);
        lv  += __shfl_xor_sync(0xffffffffu, lv,  off);
    }
    if (lane==0){ r1s[wid]=loc; r2s[wid]=lv; }
    __syncthreads();
    if (tid==0){
        g_sq[bn]  = r1s[0]+r1s[1]+r1s[2]+r1s[3];
        g_ltm[bn] = (r2s[0]+r2s[1]+r2s[2]+r2s[3]) * (1.f/100.f);
    }
}

// ------- fused nnblock with 1x2 query tiling (2 queries share candidates+x) -------
__global__ void __launch_bounds__(256) nnblock_q2(const float* __restrict__ x)
{
    extern __shared__ float sm[];
    float* s_xf = sm;                 // 8 * 40 * 45 = 14400
    float* s_q  = sm + 14400;         // 2 * 800 = 1600
    __shared__ __align__(16) float s_wk[2][M_][8];
    __shared__ float s_dot[56][2];
    __shared__ int s_c1[7], s_u2[8], s_qn[2], s_valid[2];
    __shared__ float s_sqq[2], s_scale[2];
    __shared__ int s_offq[2][52];

    int t = blockIdx.x;
    int b = t / 946; int rem = t % 946;
    int q1 = rem / 22, t2 = rem % 22;
    int tid = threadIdx.x, lane = tid & 31, w = tid >> 5;

    int c1lo = max(q1-3,0), c1hi = min(q1+3,42);
    int c2lo = max(2*t2-3,0), c2hi = min(2*t2+4,42);
    int rows = (c1hi-c1lo)*S_ + P_;   // <= 40
    int cols = (c2hi-c2lo)*S_ + P_;   // <= 45
    int r0 = c1lo*S_, c0 = c2lo*S_;

    if (tid < 7) s_c1[tid] = min(max(q1+tid-3,0),42);
    if (tid < 8) s_u2[tid] = min(max(2*t2-3+tid,0),42);
    if (tid < 2){
        int q2r = 2*t2 + tid;
        s_valid[tid] = (q2r <= 42) ? 1 : 0;
        int q2 = min(q2r, 42);
        int qn = q1*43 + q2;
        s_qn[tid] = qn;
        s_sqq[tid] = g_sq[b*N_+qn];
        s_scale[tid] = expf(-g_ltm[b*N_+qn]);
    }
    #pragma unroll
    for (int qq = 0; qq < 2; qq++){
        int q2 = min(2*t2 + qq, 42);
        const float4* src = (const float4*)(g_pe + (size_t)(b*N_ + q1*43+q2)*D_);
        if (tid < 200) ((float4*)(s_q + qq*800))[tid] = src[tid];
    }
    #pragma unroll
    for (int c = 0; c < CIN_; c++){
        const float* src = x + ((size_t)(b*CIN_+c)*H_ + r0)*W_ + c0;
        for (int r = w; r < rows; r += 8)
            for (int cc = lane; cc < cols; cc += 32)
                s_xf[c*1800 + r*45 + cc] = src[r*W_ + cc];
    }
    __syncthreads();

    // offset table (needs s_c1/s_u2; safe after the sync)
    if (tid < 98){
        int qq = tid / 49, mm = tid % 49;
        int i = mm / 7, j = mm % 7;
        s_offq[qq][mm] = (s_c1[i]*S_ - r0)*45 + (s_u2[j+qq]*S_ - c0);
    }

    // distances: 56 union candidates x 2 queries
    const float4* sq0 = (const float4*)(s_q);
    const float4* sq1 = (const float4*)(s_q + 800);
    for (int m = w; m < 56; m += 8){
        int i = m >> 3, j = m & 7;
        int cand = s_c1[i]*43 + s_u2[j];
        const float4* pc = (const float4*)(g_pe + (size_t)(b*N_+cand)*D_);
        float d0=0.f, d1=0.f;
        #pragma unroll
        for (int jj = 0; jj < 6; jj++){
            float4 a = pc[lane + jj*32];
            float4 v;
            v = sq0[lane+jj*32]; d0 = fmaf(a.x,v.x,fmaf(a.y,v.y,fmaf(a.z,v.z,fmaf(a.w,v.w,d0))));
            v = sq1[lane+jj*32]; d1 = fmaf(a.x,v.x,fmaf(a.y,v.y,fmaf(a.z,v.z,fmaf(a.w,v.w,d1))));
        }
        if (lane < 8){
            float4 a = pc[192+lane];
            float4 v;
            v = sq0[192+lane]; d0 = fmaf(a.x,v.x,fmaf(a.y,v.y,fmaf(a.z,v.z,fmaf(a.w,v.w,d0))));
            v = sq1[192+lane]; d1 = fmaf(a.x,v.x,fmaf(a.y,v.y,fmaf(a.z,v.z,fmaf(a.w,v.w,d1))));
        }
        #pragma unroll
        for (int off=16; off; off>>=1){
            d0 += __shfl_xor_sync(0xffffffffu, d0, off);
            d1 += __shfl_xor_sync(0xffffffffu, d1, off);
        }
        if (lane == 0){
            float sqc = g_sq[b*N_+cand];
            s_dot[m][0] = (cand==s_qn[0]) ? -1e9f : -(s_sqq[0]+sqc-2.f*d0)*s_scale[0];
            s_dot[m][1] = (cand==s_qn[1]) ? -1e9f : -(s_sqq[1]+sqc-2.f*d1)*s_scale[1];
        }
    }
    __syncthreads();

    // K=7 iterative softmax: warp 0 -> query 0, warp 1 -> query 1
    if (w < 2){
        int jq = w;
        int i1 = lane/7, j1 = lane%7;
        float a = s_dot[i1*8 + j1 + jq][w];
        int idx2 = lane + 32;
        bool hasb = idx2 < M_;
        float bvl = -INFINITY;
        if (hasb){ int i2 = idx2/7, j2 = idx2%7; bvl = s_dot[i2*8 + j2 + jq][w]; }
        #pragma unroll
        for (int k=0;k<K_;k++){
            float mx = fmaxf(a, bvl);
            #pragma unroll
            for (int off=16; off; off>>=1) mx = fmaxf(mx, __shfl_xor_sync(0xffffffffu, mx, off));
            float ea = expf(a - mx);
            float eb = hasb ? expf(bvl - mx) : 0.f;
            float ssum = ea + eb;
            #pragma unroll
            for (int off=16; off; off>>=1) ssum += __shfl_xor_sync(0xffffffffu, ssum, off);
            float inv = 1.f/ssum;
            float wa = ea*inv, wb = eb*inv;
            s_wk[w][lane][k] = wa;
            if (hasb) s_wk[w][idx2][k] = wb;
            a   += log1pf(-fminf(wa, 1.f-1e-6f));
            bvl += log1pf(-fminf(wb, 1.f-1e-6f));
        }
    }
    __syncthreads();

    // aggregation for both queries
    int dbase[4]; bool act[4];
    #pragma unroll
    for (int jd=0;jd<4;jd++){
        int d = tid + 256*jd;
        act[jd] = (d < D_);
        int dd = act[jd] ? d : 0;
        int c = dd/100, rm = dd%100, p1 = rm/10, p2 = rm%10;
        dbase[jd] = c*1800 + p1*45 + p2;
    }

    for (int qq = 0; qq < 2; qq++){
        if (!s_valid[qq]) continue;
        ull a01[4], a23[4], a45[4]; float a6[4];
        #pragma unroll
        for (int jd=0;jd<4;jd++){ a01[jd]=0ull; a23[jd]=0ull; a45[jd]=0ull; a6[jd]=0.f; }
        for (int m = 0; m < M_; m++){
            int o = s_offq[qq][m];
            const ull* wr = (const ull*)&s_wk[qq][m][0];
            ull w01 = wr[0], w23 = wr[1], w45 = wr[2];
            float w6 = s_wk[qq][m][6];
            #pragma unroll
            for (int jd=0;jd<4;jd++){
                float v = s_xf[dbase[jd]+o];
                ull vv = pack2s(v);
                ffma2(a01[jd], vv, w01);
                ffma2(a23[jd], vv, w23);
                ffma2(a45[jd], vv, w45);
                a6[jd] = fmaf(w6, v, a6[jd]);
            }
        }
        int n = s_qn[qq];
        #pragma unroll
        for (int jd=0;jd<4;jd++){
            if (!act[jd]) continue;
            int d = tid + 256*jd;
            float o0,o1,o2,o3,o4,o5;
            unpack2(o0,o1,a01[jd]); unpack2(o2,o3,a23[jd]); unpack2(o4,o5,a45[jd]);
            float vals[7] = {o0,o1,o2,o3,o4,o5,a6[jd]};
            #pragma unroll
            for (int k=0;k<K_;k++)
                g_nb[((size_t)(k*B_+b)*N_ + n)*D_ + d] = vals[k];
        }
    }
}

// ---------------- fold (unchanged) ----------------
__global__ void fold_kernel(const float* __restrict__ x, float* __restrict__ out)
{
    int idx = blockIdx.x*blockDim.x + threadIdx.x;
    const int total = B_*(K_+1)*CIN_*H_*W_;
    if (idx >= total) return;
    int w  = idx % W_;
    int r  = (idx / W_) % H_;
    int ch = (idx / (H_*W_)) % ((K_+1)*CIN_);
    int b  = idx / (H_*W_*(K_+1)*CIN_);

    if (ch < CIN_){
        out[idx] = x[((b*CIN_+ch)*H_+r)*W_+w];
        return;
    }
    int k = (ch - CIN_) / CIN_;
    int c = (ch - CIN_) % CIN_;

    int n1lo = (r >= P_-1) ? (r-(P_-1)+S_-1)/S_ : 0;
    int n1hi = min(N1_-1, r/S_);
    int n2lo = (w >= P_-1) ? (w-(P_-1)+S_-1)/S_ : 0;
    int n2hi = min(N1_-1, w/S_);

    float sum = 0.f; int cnt = 0;
    for (int n1=n1lo; n1<=n1hi; n1++){
        int p1 = r - n1*S_;
        for (int n2=n2lo; n2<=n2hi; n2++){
            int p2 = w - n2*S_;
            sum += g_nb[((size_t)(k*B_+b)*N_ + n1*N1_+n2)*D_ + c*100 + p1*10 + p2];
            cnt++;
        }
    }
    out[idx] = (cnt > 0) ? sum/(float)cnt : 0.f;
}

// ---------------- launch ----------------
extern "C" void kernel_launch(void* const* d_in, const int* in_sizes, int n_in,
                              void* d_out, int out_size)
{
    const float* x   = (const float*)d_in[0];
    const float* w1e = (const float*)d_in[1];
    const float* b1e = (const float*)d_in[2];
    const float* w2e = (const float*)d_in[3];
    const float* b2e = (const float*)d_in[4];
    const float* w3e = (const float*)d_in[5];
    const float* b3e = (const float*)d_in[6];
    const float* w1t = (const float*)d_in[7];
    const float* b1t = (const float*)d_in[8];
    const float* w2t = (const float*)d_in[9];
    const float* b2t = (const float*)d_in[10];
    const float* w3t = (const float*)d_in[11];
    const float* b3t = (const float*)d_in[12];

    float *t1e, *t1t, *t2e, *t2t, *xe, *ltmap;
    cudaGetSymbolAddress((void**)&t1e,   g_t1e);
    cudaGetSymbolAddress((void**)&t1t,   g_t1t);
    cudaGetSymbolAddress((void**)&t2e,   g_t2e);
    cudaGetSymbolAddress((void**)&t2t,   g_t2t);
    cudaGetSymbolAddress((void**)&xe,    g_xe);
    cudaGetSymbolAddress((void**)&ltmap, g_ltmap);

    static int attr_done = 0;
    if (!attr_done){
        cudaFuncSetAttribute(nnblock_q2,
                             cudaFuncAttributeMaxDynamicSharedMemorySize, 66*1024);
        cudaFuncSetAttribute(conv2_mma,
                             cudaFuncAttributeMaxDynamicSharedMemorySize, CSM2_TOT);
        attr_done = 1;
    }

    conv1_fused<<<dim3(49,8,B_), 256>>>(x, w1e, b1e, t1e, w1t, b1t, t1t);
    wprep_kernel<<<18, 256>>>(w2e, w2t);
    nhwc_convert<<<dim3(4,226,8), 256>>>(t1e, t1t);
    conv2_mma<<<dim3(196,2,2), 256, CSM2_TOT>>>(b2e, b2t);
    conv3x3_dual<<<dim3(49,2,B_), 256>>>(t2e, w3e, b3e, xe,    E_,
                                         t2t, w3t, b3t, ltmap, 1, F_, 0, 1);

    patches_kernel<<<B_*N_, 128>>>();
    nnblock_q2<<<B_*946, 256, 16000*sizeof(float)>>>(x);

    const int total = B_*(K_+1)*CIN_*H_*W_;
    fold_kernel<<<(total+255)/256, 256>>>(x, (float*)d_out);
}

// round 17
// speedup vs baseline: 1.1231x; 1.0011x over previous
#include <cuda_runtime.h>
#include <cuda_fp16.h>
#include <math.h>
#include <stdint.h>

#define B_ 2
#define CIN_ 8
#define H_ 224
#define W_ 224
#define F_ 64
#define E_ 8
#define P_ 10
#define S_ 5
#define K_ 7
#define N1_ 43
#define N_ 1849
#define M_ 49
#define D_ 800

typedef unsigned long long ull;
__device__ __forceinline__ void ffma2(ull &d, ull a, ull b){
    asm("fma.rn.f32x2 %0, %1, %2, %0;" : "+l"(d) : "l"(a), "l"(b));
}
__device__ __forceinline__ ull pack2s(float x){
    ull r; asm("mov.b64 %0, {%1, %1};" : "=l"(r) : "f"(x)); return r;
}
__device__ __forceinline__ void unpack2(float &x, float &y, ull v){
    asm("mov.b64 {%0, %1}, %2;" : "=f"(x), "=f"(y) : "l"(v));
}

__device__ float g_t1e[B_*F_*H_*W_];
__device__ float g_t1t[B_*F_*H_*W_];
__device__ float g_t2e[B_*F_*H_*W_];
__device__ float g_t2t[B_*F_*H_*W_];
__device__ float g_xe[B_*E_*H_*W_];
__device__ float g_ltmap[B_*H_*W_];
__device__ float g_pe[B_*N_*D_];
__device__ float g_sq[B_*N_];
__device__ float g_ltm[B_*N_];
__device__ float g_nb[K_*B_*N_*D_];
__device__ __half g_nhwc[4*226*226*64];
__device__ __half g_bt[2*9*64*64];

__device__ __forceinline__ uint32_t smem_u32(const void* p){
    uint32_t a;
    asm("{ .reg .u64 t; cvta.to.shared.u64 t, %1; cvt.u32.u64 %0, t; }" : "=r"(a) : "l"(p));
    return a;
}
__device__ __forceinline__ void sts32(uint32_t addr, uint32_t v){
    asm volatile("st.shared.b32 [%0], %1;" :: "r"(addr), "r"(v) : "memory");
}
__device__ __forceinline__ void mma_fp16(float* d, const uint32_t* a, uint32_t b0, uint32_t b1){
    asm volatile("mma.sync.aligned.m16n8k16.row.col.f32.f16.f16.f32 "
        "{%0,%1,%2,%3}, {%4,%5,%6,%7}, {%8,%9}, {%0,%1,%2,%3};"
        : "+f"(d[0]),"+f"(d[1]),"+f"(d[2]),"+f"(d[3])
        : "r"(a[0]),"r"(a[1]),"r"(a[2]),"r"(a[3]), "r"(b0),"r"(b1));
}
#define LDSM4(r, addr) \
    asm volatile("ldmatrix.sync.aligned.m8n8.x4.shared.b16 {%0,%1,%2,%3}, [%4];" \
        : "=r"((r)[0]),"=r"((r)[1]),"=r"((r)[2]),"=r"((r)[3]) : "r"(addr))

#define CW2_OFF  46656
#define CSM2_TOT (46656 + 3*64*144)   // 74304: halo + 3-shift weight group

// ---------- weight fp16 table prep ----------
__global__ void wprep_kernel(const float* __restrict__ w2e, const float* __restrict__ w2t)
{
    int ns = blockIdx.x;
    int net = ns / 9, s = ns % 9;
    int dr = s / 3, dc = s % 3;
    const float* w = net ? w2t : w2e;
    int tid = threadIdx.x;
    for (int j = 0; j < 16; j++){
        int idx = tid + j*256;
        int oc = idx >> 6, ic = idx & 63;
        float v = w[((oc*64 + ic)*3 + dr)*3 + dc];
        g_bt[ns*4096 + idx] = __float2half_rn(v);
    }
}

// ---------- t1 planar fp32 -> padded NHWC fp16 ----------
__global__ void nhwc_convert(const float* __restrict__ t1e, const float* __restrict__ t1t)
{
    __shared__ float s[64][33];
    int bn = blockIdx.x;
    int b = bn >> 1, net = bn & 1;
    int rp = blockIdx.y;
    int cp0 = blockIdx.z * 32;
    int tid = threadIdx.x, lane = tid & 31, wid = tid >> 5;
    int r = rp - 1;
    const float* src = (net ? t1t : t1e) + (size_t)b*F_*H_*W_;

    for (int ic = wid; ic < 64; ic += 8){
        int c = cp0 + lane - 1;
        float v = 0.f;
        if (r >= 0 && r < H_ && c >= 0 && c < W_)
            v = src[(size_t)ic*H_*W_ + r*W_ + c];
        s[ic][lane] = v;
    }
    __syncthreads();

    uint32_t* dst = (uint32_t*)g_nhwc;
    for (int j = 0; j < 4; j++){
        int w = tid + j*256;
        int p = w >> 5, wl = w & 31;
        int cp = cp0 + p;
        if (cp >= 226) continue;
        __half h0 = __float2half_rn(s[2*wl][p]);
        __half h1 = __float2half_rn(s[2*wl+1][p]);
        uint32_t hp = (uint32_t)__half_as_ushort(h0) | ((uint32_t)__half_as_ushort(h1) << 16);
        dst[((size_t)(bn*226 + rp)*226 + cp)*32 + wl] = hp;
    }
}

// ---------- conv2: mma.sync fp16, 3-shift weight groups (6 syncs) ----------
__global__ void __launch_bounds__(256, 2)
conv2_mma(const float* __restrict__ b2e, const float* __restrict__ b2t)
{
    extern __shared__ char smem[];
    int bx = blockIdx.x;
    int net = blockIdx.y, b = blockIdx.z;
    int bn = b*2 + net;
    int ty = bx / 14, tx = bx % 14;
    int r0 = ty*16, c0 = tx*16;
    int tid = threadIdx.x, lane = tid & 31, w = tid >> 5;
    uint32_t smb = smem_u32(smem);

    const uint32_t* nh = (const uint32_t*)g_nhwc;
    for (int t = w; t < 324; t += 8){
        int hr = t / 18, hc = t % 18;
        const uint32_t* src = nh + ((size_t)(bn*226 + r0+hr)*226 + (c0+hc))*32;
        sts32(smb + t*144 + lane*4, src[lane]);
    }

    float acc[2][8][4];
    #pragma unroll
    for (int rr=0;rr<2;rr++)
        #pragma unroll
        for (int nt=0;nt<8;nt++)
            #pragma unroll
            for (int i=0;i<4;i++) acc[rr][nt][i]=0.f;

    int m15 = lane & 15;
    uint32_t a_t = smb + (uint32_t)m15*144 + ((lane & 16) ? 16u : 0u);
    int ocb = (lane & 7) + ((lane & 16) ? 8 : 0);
    uint32_t b_base = smb + CW2_OFF + (uint32_t)ocb*144 + ((lane & 8) ? 16u : 0u);

    const uint32_t* bt = (const uint32_t*)g_bt + (size_t)net*9*64*32;

    for (int dr = 0; dr < 3; dr++){
        __syncthreads();   // prev weight group consumed (and halo ready before dr=0)
        for (int rr = w; rr < 192; rr += 8){
            int sg = rr >> 6, oc = rr & 63;
            const uint32_t* src = bt + ((size_t)(dr*3 + sg)*2048 + oc*32 + lane);
            sts32(smb + CW2_OFF + rr*144 + lane*4, *src);
        }
        __syncthreads();

        for (int dc = 0; dc < 3; dc++){
            uint32_t a0 = a_t + (uint32_t)((2*w     + dr)*18 + dc)*144;
            uint32_t a1 = a_t + (uint32_t)((2*w + 1 + dr)*18 + dc)*144;
            uint32_t b_dc = b_base + (uint32_t)dc*9216;
            #pragma unroll
            for (int ks = 0; ks < 4; ks++){
                uint32_t ah0[4], ah1[4];
                LDSM4(ah0, a0 + ks*32);
                LDSM4(ah1, a1 + ks*32);
                #pragma unroll
                for (int p = 0; p < 4; p++){
                    uint32_t wh[4];
                    LDSM4(wh, b_dc + (uint32_t)(p*16)*144 + ks*32);
                    mma_fp16(acc[0][2*p],   ah0, wh[0], wh[1]);
                    mma_fp16(acc[0][2*p+1], ah0, wh[2], wh[3]);
                    mma_fp16(acc[1][2*p],   ah1, wh[0], wh[1]);
                    mma_fp16(acc[1][2*p+1], ah1, wh[2], wh[3]);
                }
            }
        }
    }

    const float* bias = net ? b2t : b2e;
    float* outp = (net ? g_t2t : g_t2e) + (size_t)b*F_*H_*W_;
    int pc = lane >> 2;
    int oc_b = (lane & 3) * 2;
    #pragma unroll
    for (int rr = 0; rr < 2; rr++){
        int orow = r0 + 2*w + rr;
        #pragma unroll
        for (int nt = 0; nt < 8; nt++){
            int oc = nt*8 + oc_b;
            float bv0 = bias[oc], bv1 = bias[oc+1];
            size_t base0 = (size_t)oc*(H_*W_) + (size_t)orow*W_ + c0;
            outp[base0 + pc]               = fmaxf(acc[rr][nt][0] + bv0, 0.f);
            outp[base0 + H_*W_ + pc]       = fmaxf(acc[rr][nt][1] + bv1, 0.f);
            outp[base0 + pc + 8]           = fmaxf(acc[rr][nt][2] + bv0, 0.f);
            outp[base0 + H_*W_ + pc + 8]   = fmaxf(acc[rr][nt][3] + bv1, 0.f);
        }
    }
}

// ============ conv1 fused (FFMA2, unchanged) ============
__global__ void __launch_bounds__(256, 2) conv1_fused(
    const float* __restrict__ x,
    const float* __restrict__ wA, const float* __restrict__ bA, float* __restrict__ outA,
    const float* __restrict__ wB, const float* __restrict__ bB, float* __restrict__ outB)
{
    __shared__ float s_in[2][34*34];
    __shared__ __align__(8) float s_w[2][9*16];
    int b = blockIdx.z, oc0 = blockIdx.y * 8;
    int tile = blockIdx.x, tx = tile % 7, ty = tile / 7;
    int x0 = tx*32, y0 = ty*32;
    int tid = threadIdx.x, lx = tid & 31, ly = tid >> 5;

    int goff[5];
    #pragma unroll
    for (int j=0;j<5;j++){
        int i = tid + j*256; goff[j] = -1;
        if (i < 34*34){
            int r = i/34, c = i%34, gr = y0-1+r, gc = x0-1+c;
            goff[j] = (gr>=0 && gr<H_ && gc>=0 && gc<W_) ? gr*W_+gc : -1;
        }
    }
    const float* inbase = x + (size_t)b*CIN_*H_*W_;
    const float* wp = wA; int wslot = 0;
    if (tid < 144){
        int o = tid/9, kk = tid%9;
        wslot = kk*16 + o;
        wp = (o < 8) ? (wA + ((oc0+o)*CIN_)*9 + kk)
                     : (wB + ((oc0+o-8)*CIN_)*9 + kk);
    }
    {
        #pragma unroll
        for (int j=0;j<5;j++){
            int i = tid + j*256;
            if (i < 34*34) s_in[0][i] = (goff[j] >= 0) ? inbase[goff[j]] : 0.f;
        }
        if (tid < 144) s_w[0][wslot] = wp[0];
    }
    __syncthreads();

    ull acc[4][8];
    #pragma unroll
    for (int p=0;p<4;p++)
        #pragma unroll
        for (int o=0;o<8;o++) acc[p][o]=0ull;

    for (int ic=0; ic<CIN_; ic++){
        int buf = ic & 1;
        if (ic+1 < CIN_){
            const float* inp = inbase + (size_t)(ic+1)*H_*W_;
            int nb = buf^1;
            #pragma unroll
            for (int j=0;j<5;j++){
                int i = tid + j*256;
                if (i < 34*34) s_in[nb][i] = (goff[j] >= 0) ? inp[goff[j]] : 0.f;
            }
            if (tid < 144) s_w[nb][wslot] = wp[(ic+1)*9];
        }
        const float* si = s_in[buf];
        #pragma unroll
        for (int dr=0;dr<3;dr++){
            #pragma unroll
            for (int dc=0;dc<3;dc++){
                int kk = dr*3+dc;
                ull v0 = pack2s(si[(ly   +dr)*34 + lx+dc]);
                ull v1 = pack2s(si[(ly+ 8+dr)*34 + lx+dc]);
                ull v2 = pack2s(si[(ly+16+dr)*34 + lx+dc]);
                ull v3 = pack2s(si[(ly+24+dr)*34 + lx+dc]);
                const ull* wrow = (const ull*)&s_w[buf][kk*16];
                #pragma unroll
                for (int op=0;op<8;op++){
                    ull w2 = wrow[op];
                    ffma2(acc[0][op], v0, w2);
                    ffma2(acc[1][op], v1, w2);
                    ffma2(acc[2][op], v2, w2);
                    ffma2(acc[3][op], v3, w2);
                }
            }
        }
        __syncthreads();
    }

    #pragma unroll
    for (int op=0;op<8;op++){
        #pragma unroll
        for (int h=0;h<2;h++){
            int o = op*2+h;
            int oc = oc0 + ((o<8) ? o : o-8);
            float bv = (o<8) ? bA[oc] : bB[oc];
            float* opt = (o<8) ? outA : outB;
            #pragma unroll
            for (int p=0;p<4;p++){
                float a0,a1; unpack2(a0,a1,acc[p][op]);
                float r = fmaxf((h ? a1 : a0) + bv, 0.f);
                opt[((size_t)(b*F_+oc)*H_ + (y0+ly+p*8))*W_ + x0+lx] = r;
            }
        }
    }
}

// ---------------- dual 3x3 conv (layer 3), FFMA2 (unchanged) ----------------
__global__ void __launch_bounds__(256, 4) conv3x3_dual(
    const float* __restrict__ inA, const float* __restrict__ wA,
    const float* __restrict__ bA, float* __restrict__ outA, int CoutA,
    const float* __restrict__ inB, const float* __restrict__ wB,
    const float* __restrict__ bB, float* __restrict__ outB, int CoutB,
    int Cin, int relu, int gA)
{
    __shared__ float s_in[34*34];
    __shared__ __align__(8) float s_w[9*8];
    int b = blockIdx.z, ocg = blockIdx.y;
    const float* in; const float* wgt; const float* bias; float* out; int Cout;
    if (ocg < gA){ in=inA; wgt=wA; bias=bA; out=outA; Cout=CoutA; }
    else { ocg -= gA; in=inB; wgt=wB; bias=bB; out=outB; Cout=CoutB; }

    int tile = blockIdx.x, tx = tile % 7, ty = tile / 7;
    int x0 = tx*32, y0 = ty*32;
    int tid = threadIdx.x, lx = tid & 31, ly = tid >> 5;

    ull acc[4][4];
    #pragma unroll
    for (int p=0;p<4;p++)
        #pragma unroll
        for (int o=0;o<4;o++) acc[p][o]=0ull;

    for (int ic=0; ic<Cin; ic++){
        const float* inp = in + ((size_t)(b*Cin + ic))*H_*W_;
        for (int i=tid; i<34*34; i+=256){
            int r = i/34, c = i%34, gr = y0-1+r, gc = x0-1+c;
            float v = 0.f;
            if (gr>=0 && gr<H_ && gc>=0 && gc<W_) v = inp[gr*W_+gc];
            s_in[i] = v;
        }
        if (tid < 72){
            int o = tid/9, kk = tid%9;
            int oc = ocg*8+o;
            s_w[kk*8+o] = (oc<Cout) ? wgt[(oc*Cin+ic)*9 + kk] : 0.f;
        }
        __syncthreads();
        #pragma unroll
        for (int dr=0;dr<3;dr++){
            #pragma unroll
            for (int dc=0;dc<3;dc++){
                int kk = dr*3+dc;
                ull v0 = pack2s(s_in[(ly   +dr)*34 + lx+dc]);
                ull v1 = pack2s(s_in[(ly+ 8+dr)*34 + lx+dc]);
                ull v2 = pack2s(s_in[(ly+16+dr)*34 + lx+dc]);
                ull v3 = pack2s(s_in[(ly+24+dr)*34 + lx+dc]);
                const ull* wrow = (const ull*)&s_w[kk*8];
                #pragma unroll
                for (int op=0;op<4;op++){
                    ull w2 = wrow[op];
                    ffma2(acc[0][op], v0, w2);
                    ffma2(acc[1][op], v1, w2);
                    ffma2(acc[2][op], v2, w2);
                    ffma2(acc[3][op], v3, w2);
                }
            }
        }
        __syncthreads();
    }

    #pragma unroll
    for (int op=0;op<4;op++){
        #pragma unroll
        for (int h=0;h<2;h++){
            int o = op*2+h;
            int oc = ocg*8+o;
            if (oc < Cout){
                float bv = bias[oc];
                #pragma unroll
                for (int p=0;p<4;p++){
                    float a0,a1; unpack2(a0,a1,acc[p][op]);
                    float r = (h ? a1 : a0) + bv;
                    if (relu) r = fmaxf(r, 0.f);
                    out[((size_t)(b*Cout+oc)*H_ + (y0+ly+p*8))*W_ + x0+lx] = r;
                }
            }
        }
    }
}

// ---------------- patches (unchanged) ----------------
__global__ void patches_kernel()
{
    int bn = blockIdx.x;
    int b = bn / N_, n = bn % N_;
    int n1 = n / N1_, n2 = n % N1_;
    int r0 = n1*S_, c0 = n2*S_;
    int tid = threadIdx.x;

    float loc = 0.f;
    for (int d=tid; d<D_; d+=128){
        int c = d/100, rem = d%100, p1 = rem/10, p2 = rem%10;
        float v = g_xe[((b*E_+c)*H_ + r0+p1)*W_ + c0+p2];
        g_pe[(size_t)bn*D_ + d] = v;
        loc += v*v;
    }
    float lv = 0.f;
    if (tid < 100){
        int p1 = tid/10, p2 = tid%10;
        lv = g_ltmap[(b*H_ + r0+p1)*W_ + c0+p2];
    }
    __shared__ float r1s[4], r2s[4];
    int lane = tid & 31, wid = tid >> 5;
    #pragma unroll
    for (int off=16; off; off>>=1){
        loc += __shfl_xor_sync(0xffffffffu, loc, off);
        lv  += __shfl_xor_sync(0xffffffffu, lv,  off);
    }
    if (lane==0){ r1s[wid]=loc; r2s[wid]=lv; }
    __syncthreads();
    if (tid==0){
        g_sq[bn]  = r1s[0]+r1s[1]+r1s[2]+r1s[3];
        g_ltm[bn] = (r2s[0]+r2s[1]+r2s[2]+r2s[3]) * (1.f/100.f);
    }
}

// ------- nnblock q2 with fp16 x-staging (smem 64 -> 35 KB) -------
__global__ void __launch_bounds__(256) nnblock_q2(const float* __restrict__ x)
{
    extern __shared__ float sm[];
    float* s_q  = sm;                       // 1600 floats
    __half* s_xh = (__half*)(sm + 1600);    // 8*1800 = 14400 halfs
    __shared__ __align__(16) float s_wk[2][M_][8];
    __shared__ float s_dot[56][2];
    __shared__ int s_c1[7], s_u2[8], s_qn[2], s_valid[2];
    __shared__ float s_sqq[2], s_scale[2];
    __shared__ int s_offq[2][52];

    int t = blockIdx.x;
    int b = t / 946; int rem = t % 946;
    int q1 = rem / 22, t2 = rem % 22;
    int tid = threadIdx.x, lane = tid & 31, w = tid >> 5;

    int c1lo = max(q1-3,0), c1hi = min(q1+3,42);
    int c2lo = max(2*t2-3,0), c2hi = min(2*t2+4,42);
    int rows = (c1hi-c1lo)*S_ + P_;
    int cols = (c2hi-c2lo)*S_ + P_;
    int r0 = c1lo*S_, c0 = c2lo*S_;

    if (tid < 7) s_c1[tid] = min(max(q1+tid-3,0),42);
    if (tid < 8) s_u2[tid] = min(max(2*t2-3+tid,0),42);
    if (tid < 2){
        int q2r = 2*t2 + tid;
        s_valid[tid] = (q2r <= 42) ? 1 : 0;
        int q2 = min(q2r, 42);
        int qn = q1*43 + q2;
        s_qn[tid] = qn;
        s_sqq[tid] = g_sq[b*N_+qn];
        s_scale[tid] = expf(-g_ltm[b*N_+qn]);
    }
    #pragma unroll
    for (int qq = 0; qq < 2; qq++){
        int q2 = min(2*t2 + qq, 42);
        const float4* src = (const float4*)(g_pe + (size_t)(b*N_ + q1*43+q2)*D_);
        if (tid < 200) ((float4*)(s_q + qq*800))[tid] = src[tid];
    }
    #pragma unroll
    for (int c = 0; c < CIN_; c++){
        const float* src = x + ((size_t)(b*CIN_+c)*H_ + r0)*W_ + c0;
        for (int r = w; r < rows; r += 8)
            for (int cc = lane; cc < cols; cc += 32)
                s_xh[c*1800 + r*45 + cc] = __float2half_rn(src[r*W_ + cc]);
    }
    __syncthreads();

    if (tid < 98){
        int qq = tid / 49, mm = tid % 49;
        int i = mm / 7, j = mm % 7;
        s_offq[qq][mm] = (s_c1[i]*S_ - r0)*45 + (s_u2[j+qq]*S_ - c0);
    }

    const float4* sq0 = (const float4*)(s_q);
    const float4* sq1 = (const float4*)(s_q + 800);
    for (int m = w; m < 56; m += 8){
        int i = m >> 3, j = m & 7;
        int cand = s_c1[i]*43 + s_u2[j];
        const float4* pc = (const float4*)(g_pe + (size_t)(b*N_+cand)*D_);
        float d0=0.f, d1=0.f;
        #pragma unroll
        for (int jj = 0; jj < 6; jj++){
            float4 a = pc[lane + jj*32];
            float4 v;
            v = sq0[lane+jj*32]; d0 = fmaf(a.x,v.x,fmaf(a.y,v.y,fmaf(a.z,v.z,fmaf(a.w,v.w,d0))));
            v = sq1[lane+jj*32]; d1 = fmaf(a.x,v.x,fmaf(a.y,v.y,fmaf(a.z,v.z,fmaf(a.w,v.w,d1))));
        }
        if (lane < 8){
            float4 a = pc[192+lane];
            float4 v;
            v = sq0[192+lane]; d0 = fmaf(a.x,v.x,fmaf(a.y,v.y,fmaf(a.z,v.z,fmaf(a.w,v.w,d0))));
            v = sq1[192+lane]; d1 = fmaf(a.x,v.x,fmaf(a.y,v.y,fmaf(a.z,v.z,fmaf(a.w,v.w,d1))));
        }
        #pragma unroll
        for (int off=16; off; off>>=1){
            d0 += __shfl_xor_sync(0xffffffffu, d0, off);
            d1 += __shfl_xor_sync(0xffffffffu, d1, off);
        }
        if (lane == 0){
            float sqc = g_sq[b*N_+cand];
            s_dot[m][0] = (cand==s_qn[0]) ? -1e9f : -(s_sqq[0]+sqc-2.f*d0)*s_scale[0];
            s_dot[m][1] = (cand==s_qn[1]) ? -1e9f : -(s_sqq[1]+sqc-2.f*d1)*s_scale[1];
        }
    }
    __syncthreads();

    if (w < 2){
        int jq = w;
        int i1 = lane/7, j1 = lane%7;
        float a = s_dot[i1*8 + j1 + jq][w];
        int idx2 = lane + 32;
        bool hasb = idx2 < M_;
        float bvl = -INFINITY;
        if (hasb){ int i2 = idx2/7, j2 = idx2%7; bvl = s_dot[i2*8 + j2 + jq][w]; }
        #pragma unroll
        for (int k=0;k<K_;k++){
            float mx = fmaxf(a, bvl);
            #pragma unroll
            for (int off=16; off; off>>=1) mx = fmaxf(mx, __shfl_xor_sync(0xffffffffu, mx, off));
            float ea = expf(a - mx);
            float eb = hasb ? expf(bvl - mx) : 0.f;
            float ssum = ea + eb;
            #pragma unroll
            for (int off=16; off; off>>=1) ssum += __shfl_xor_sync(0xffffffffu, ssum, off);
            float inv = 1.f/ssum;
            float wa = ea*inv, wb = eb*inv;
            s_wk[w][lane][k] = wa;
            if (hasb) s_wk[w][idx2][k] = wb;
            a   += log1pf(-fminf(wa, 1.f-1e-6f));
            bvl += log1pf(-fminf(wb, 1.f-1e-6f));
        }
    }
    __syncthreads();

    int dbase[4]; bool act[4];
    #pragma unroll
    for (int jd=0;jd<4;jd++){
        int d = tid + 256*jd;
        act[jd] = (d < D_);
        int dd = act[jd] ? d : 0;
        int c = dd/100, rm = dd%100, p1 = rm/10, p2 = rm%10;
        dbase[jd] = c*1800 + p1*45 + p2;
    }

    for (int qq = 0; qq < 2; qq++){
        if (!s_valid[qq]) continue;
        ull a01[4], a23[4], a45[4]; float a6[4];
        #pragma unroll
        for (int jd=0;jd<4;jd++){ a01[jd]=0ull; a23[jd]=0ull; a45[jd]=0ull; a6[jd]=0.f; }
        for (int m = 0; m < M_; m++){
            int o = s_offq[qq][m];
            const ull* wr = (const ull*)&s_wk[qq][m][0];
            ull w01 = wr[0], w23 = wr[1], w45 = wr[2];
            float w6 = s_wk[qq][m][6];
            #pragma unroll
            for (int jd=0;jd<4;jd++){
                float v = __half2float(s_xh[dbase[jd]+o]);
                ull vv = pack2s(v);
                ffma2(a01[jd], vv, w01);
                ffma2(a23[jd], vv, w23);
                ffma2(a45[jd], vv, w45);
                a6[jd] = fmaf(w6, v, a6[jd]);
            }
        }
        int n = s_qn[qq];
        #pragma unroll
        for (int jd=0;jd<4;jd++){
            if (!act[jd]) continue;
            int d = tid + 256*jd;
            float o0,o1,o2,o3,o4,o5;
            unpack2(o0,o1,a01[jd]); unpack2(o2,o3,a23[jd]); unpack2(o4,o5,a45[jd]);
            float vals[7] = {o0,o1,o2,o3,o4,o5,a6[jd]};
            #pragma unroll
            for (int k=0;k<K_;k++)
                g_nb[((size_t)(k*B_+b)*N_ + n)*D_ + d] = vals[k];
        }
    }
}

// ---------------- fold (unchanged) ----------------
__global__ void fold_kernel(const float* __restrict__ x, float* __restrict__ out)
{
    int idx = blockIdx.x*blockDim.x + threadIdx.x;
    const int total = B_*(K_+1)*CIN_*H_*W_;
    if (idx >= total) return;
    int w  = idx % W_;
    int r  = (idx / W_) % H_;
    int ch = (idx / (H_*W_)) % ((K_+1)*CIN_);
    int b  = idx / (H_*W_*(K_+1)*CIN_);

    if (ch < CIN_){
        out[idx] = x[((b*CIN_+ch)*H_+r)*W_+w];
        return;
    }
    int k = (ch - CIN_) / CIN_;
    int c = (ch - CIN_) % CIN_;

    int n1lo = (r >= P_-1) ? (r-(P_-1)+S_-1)/S_ : 0;
    int n1hi = min(N1_-1, r/S_);
    int n2lo = (w >= P_-1) ? (w-(P_-1)+S_-1)/S_ : 0;
    int n2hi = min(N1_-1, w/S_);

    float sum = 0.f; int cnt = 0;
    for (int n1=n1lo; n1<=n1hi; n1++){
        int p1 = r - n1*S_;
        for (int n2=n2lo; n2<=n2hi; n2++){
            int p2 = w - n2*S_;
            sum += g_nb[((size_t)(k*B_+b)*N_ + n1*N1_+n2)*D_ + c*100 + p1*10 + p2];
            cnt++;
        }
    }
    out[idx] = (cnt > 0) ? sum/(float)cnt : 0.f;
}

// ---------------- launch ----------------
extern "C" void kernel_launch(void* const* d_in, const int* in_sizes, int n_in,
                              void* d_out, int out_size)
{
    const float* x   = (const float*)d_in[0];
    const float* w1e = (const float*)d_in[1];
    const float* b1e = (const float*)d_in[2];
    const float* w2e = (const float*)d_in[3];
    const float* b2e = (const float*)d_in[4];
    const float* w3e = (const float*)d_in[5];
    const float* b3e = (const float*)d_in[6];
    const float* w1t = (const float*)d_in[7];
    const float* b1t = (const float*)d_in[8];
    const float* w2t = (const float*)d_in[9];
    const float* b2t = (const float*)d_in[10];
    const float* w3t = (const float*)d_in[11];
    const float* b3t = (const float*)d_in[12];

    float *t1e, *t1t, *t2e, *t2t, *xe, *ltmap;
    cudaGetSymbolAddress((void**)&t1e,   g_t1e);
    cudaGetSymbolAddress((void**)&t1t,   g_t1t);
    cudaGetSymbolAddress((void**)&t2e,   g_t2e);
    cudaGetSymbolAddress((void**)&t2t,   g_t2t);
    cudaGetSymbolAddress((void**)&xe,    g_xe);
    cudaGetSymbolAddress((void**)&ltmap, g_ltmap);

    static int attr_done = 0;
    if (!attr_done){
        cudaFuncSetAttribute(nnblock_q2,
                             cudaFuncAttributeMaxDynamicSharedMemorySize, 40*1024);
        cudaFuncSetAttribute(conv2_mma,
                             cudaFuncAttributeMaxDynamicSharedMemorySize, CSM2_TOT);
        attr_done = 1;
    }

    conv1_fused<<<dim3(49,8,B_), 256>>>(x, w1e, b1e, t1e, w1t, b1t, t1t);
    wprep_kernel<<<18, 256>>>(w2e, w2t);
    nhwc_convert<<<dim3(4,226,8), 256>>>(t1e, t1t);
    conv2_mma<<<dim3(196,2,2), 256, CSM2_TOT>>>(b2e, b2t);
    conv3x3_dual<<<dim3(49,2,B_), 256>>>(t2e, w3e, b3e, xe,    E_,
                                         t2t, w3t, b3t, ltmap, 1, F_, 0, 1);

    patches_kernel<<<B_*N_, 128>>>();
    nnblock_q2<<<B_*946, 256, (1600 + 7200)*sizeof(float)>>>(x);

    const int total = B_*(K_+1)*CIN_*H_*W_;
    fold_kernel<<<(total+255)/256, 256>>>(x, (float*)d_out);
}